// round 16
// baseline (speedup 1.0000x reference)
#include <cuda_runtime.h>
#include <cuda_bf16.h>
#include <cuda_fp16.h>
#include <cstdint>

#define MAX_N 50000
#define MAX_E 800000
#define IN_CH 128
#define HID_CH 256
#define OUT_CH 128
#define DMAX 128

// ---------------------------------------------------------------------------
// Device scratch (allocation-free rule). Zero-initialized at module load;
// g_fill is restored to zero by agg2 every call (deterministic invariant).
// ---------------------------------------------------------------------------
__device__ __align__(16) __half g_a1[(size_t)MAX_N * 256];    // layer-1 A, fp16
__device__ __align__(16) __half g_a2[(size_t)MAX_N * 256];    // layer-2 A, fp16
__device__ __align__(16) __half g_w1[256 * 256];              // composite W fp16
__device__ __align__(16) __half g_w2[256 * 256];
__device__ __align__(16) __half g_x16[(size_t)MAX_N * 128];   // x, fp16 (gather copy)
__device__ __align__(16) __half g_t16[(size_t)MAX_N * 128];   // layer-2 t half, fp16
__device__ float g_r[(size_t)MAX_N * 128];                    // layer-2 r half, fp32
__device__ int g_fill[MAX_N];                                 // degree counters
__device__ int g_colpad[(size_t)MAX_N * DMAX];                // padded CSR

// ---------------------------------------------------------------------------
// Helpers
// ---------------------------------------------------------------------------
__device__ __forceinline__ uint32_t smem_to_u32(const void* p) {
    uint32_t a;
    asm("{ .reg .u64 t; cvta.to.shared.u64 t, %1; cvt.u32.u64 %0, t; }"
        : "=r"(a) : "l"(p));
    return a;
}

__device__ __forceinline__ void ldsm_x4(uint32_t* r, uint32_t addr) {
    asm volatile("ldmatrix.sync.aligned.m8n8.x4.shared.b16 {%0,%1,%2,%3}, [%4];"
        : "=r"(r[0]), "=r"(r[1]), "=r"(r[2]), "=r"(r[3]) : "r"(addr));
}

__device__ __forceinline__ void mma16816(float* d, const uint32_t* a,
                                          const uint32_t* b) {
    asm volatile(
        "mma.sync.aligned.m16n8k16.row.col.f32.f16.f16.f32 "
        "{%0,%1,%2,%3}, {%4,%5,%6,%7}, {%8,%9}, {%0,%1,%2,%3};"
        : "+f"(d[0]), "+f"(d[1]), "+f"(d[2]), "+f"(d[3])
        : "r"(a[0]), "r"(a[1]), "r"(a[2]), "r"(a[3]), "r"(b[0]), "r"(b[1]));
}

__device__ __forceinline__ void cp16(uint32_t dst, const void* src, bool pred) {
    int sz = pred ? 16 : 0;
    asm volatile("cp.async.cg.shared.global [%0], [%1], 16, %2;"
        :: "r"(dst), "l"(src), "r"(sz));
}

// ---------------------------------------------------------------------------
// Kernel 1 (single edge pass): padded-CSR fill with per-block dtype self-sniff
//   blocks [0,EB):          edge fill (slot = atomicAdd(fill[dst]))
//   blocks [EB,EB+512):     fp16 weight prep
//   blocks [EB+512,+XB):    x -> fp16 gather copy
// ---------------------------------------------------------------------------
__global__ void fill_prep_kernel(const void* __restrict__ ei, int E, int N, int EB,
                                 const float* __restrict__ W1l,
                                 const float* __restrict__ W1r,
                                 const float* __restrict__ W2l,
                                 const float* __restrict__ W2r,
                                 const float* __restrict__ x) {
    int b = blockIdx.x, t = threadIdx.x;
    if (b < EB) {
        __shared__ int red[256];
        red[t] = reinterpret_cast<const int*>(ei)[2 * t + 1];
        __syncthreads();
        for (int s = 128; s > 0; s >>= 1) {
            if (t < s) red[t] |= red[t + s];
            __syncthreads();
        }
        bool is64 = (red[0] == 0);
        int e = b * 256 + t;
        if (e >= E) return;
        int src, dst;
        if (is64) {
            src = (int)reinterpret_cast<const long long*>(ei)[e];
            dst = (int)reinterpret_cast<const long long*>(ei)[(size_t)E + e];
        } else {
            src = reinterpret_cast<const int*>(ei)[e];
            dst = reinterpret_cast<const int*>(ei)[(size_t)E + e];
        }
        if ((unsigned)src >= (unsigned)N || (unsigned)dst >= (unsigned)N) return;
        int slot = atomicAdd(&g_fill[dst], 1);
        if (slot < DMAX)
            g_colpad[(size_t)dst * DMAX + slot] = src;
    } else if (b < EB + 512) {
        int wb = b - EB;
        int idx = (wb & 255) * 256 + t;
        int o = idx >> 8, k = idx & 255;
        if (wb < 256) {
            float v = (k < 128) ? W1r[o * 128 + k] : W1l[o * 128 + (k - 128)];
            g_w1[idx] = __float2half_rn(v);
        } else {
            float v = (o < 128) ? W2l[o * 256 + k] : W2r[(o - 128) * 256 + k];
            g_w2[idx] = __float2half_rn(v);
        }
    } else {
        int idx = (b - EB - 512) * 256 + t;
        if (idx >= N * 64) return;
        float2 v = reinterpret_cast<const float2*>(x)[idx];
        reinterpret_cast<__half2*>(g_x16)[idx] = __float22half2_rn(v);
    }
}

// ---------------------------------------------------------------------------
// Layer-1 aggregation (padded CSR, unroll-8) -> single fp16 A:
//   cols 0..127 <- fp16(x[n]);  cols 128..255 <- fp16(mean_{s} x16[s])
// ---------------------------------------------------------------------------
__global__ void agg1_kernel(const float* __restrict__ x, int N) {
    int w = (blockIdx.x * blockDim.x + threadIdx.x) >> 5;
    int l = threadIdx.x & 31;
    if (w >= N) return;
    int deg = g_fill[w];
    int end = min(deg, DMAX);
    const int* col = g_colpad + (size_t)w * DMAX;
    const uint2* X2 = reinterpret_cast<const uint2*>(g_x16);
    float2 a0 = make_float2(0.f, 0.f), a1 = make_float2(0.f, 0.f);
    int i = 0;
    for (; i + 7 < end; i += 8) {
        int s[8];
#pragma unroll
        for (int u = 0; u < 8; u++) s[u] = col[i + u];
        uint2 v[8];
#pragma unroll
        for (int u = 0; u < 8; u++) v[u] = X2[(size_t)s[u] * 32 + l];
#pragma unroll
        for (int u = 0; u < 8; u++) {
            float2 f0 = __half22float2(*reinterpret_cast<__half2*>(&v[u].x));
            float2 f1 = __half22float2(*reinterpret_cast<__half2*>(&v[u].y));
            a0.x += f0.x; a0.y += f0.y; a1.x += f1.x; a1.y += f1.y;
        }
    }
    for (; i < end; i++) {
        uint2 v = X2[(size_t)col[i] * 32 + l];
        float2 f0 = __half22float2(*reinterpret_cast<__half2*>(&v.x));
        float2 f1 = __half22float2(*reinterpret_cast<__half2*>(&v.y));
        a0.x += f0.x; a0.y += f0.y; a1.x += f1.x; a1.y += f1.y;
    }
    float inv = 1.f / fmaxf((float)deg, 1.f);
    size_t base = (size_t)w * 256 + 128 + l * 4;
    *reinterpret_cast<__half2*>(g_a1 + base) =
        __halves2half2(__float2half_rn(a0.x * inv), __float2half_rn(a0.y * inv));
    *reinterpret_cast<__half2*>(g_a1 + base + 2) =
        __halves2half2(__float2half_rn(a1.x * inv), __float2half_rn(a1.y * inv));
    float4 xr = reinterpret_cast<const float4*>(x)[(size_t)w * 32 + l];
    base = (size_t)w * 256 + l * 4;
    *reinterpret_cast<__half2*>(g_a1 + base) =
        __halves2half2(__float2half_rn(xr.x), __float2half_rn(xr.y));
    *reinterpret_cast<__half2*>(g_a1 + base + 2) =
        __halves2half2(__float2half_rn(xr.z), __float2half_rn(xr.w));
}

// ---------------------------------------------------------------------------
// Layer-2 aggregation (padded CSR, unroll-8) + combine; restores g_fill to 0.
//   out[n][c] = mean_{s in N(n)} t16[s][c] + r[n][c]
// ---------------------------------------------------------------------------
__global__ void agg2_kernel(float* __restrict__ out, int N) {
    int w = (blockIdx.x * blockDim.x + threadIdx.x) >> 5;
    int l = threadIdx.x & 31;
    if (w >= N) return;
    int deg = g_fill[w];
    int end = min(deg, DMAX);
    const int* col = g_colpad + (size_t)w * DMAX;
    const uint2* T2 = reinterpret_cast<const uint2*>(g_t16);
    float2 a0 = make_float2(0.f, 0.f), a1 = make_float2(0.f, 0.f);
    int i = 0;
    for (; i + 7 < end; i += 8) {
        int s[8];
#pragma unroll
        for (int u = 0; u < 8; u++) s[u] = col[i + u];
        uint2 v[8];
#pragma unroll
        for (int u = 0; u < 8; u++) v[u] = T2[(size_t)s[u] * 32 + l];
#pragma unroll
        for (int u = 0; u < 8; u++) {
            float2 f0 = __half22float2(*reinterpret_cast<__half2*>(&v[u].x));
            float2 f1 = __half22float2(*reinterpret_cast<__half2*>(&v[u].y));
            a0.x += f0.x; a0.y += f0.y; a1.x += f1.x; a1.y += f1.y;
        }
    }
    for (; i < end; i++) {
        uint2 v = T2[(size_t)col[i] * 32 + l];
        float2 f0 = __half22float2(*reinterpret_cast<__half2*>(&v.x));
        float2 f1 = __half22float2(*reinterpret_cast<__half2*>(&v.y));
        a0.x += f0.x; a0.y += f0.y; a1.x += f1.x; a1.y += f1.y;
    }
    float inv = 1.f / fmaxf((float)deg, 1.f);
    float4 r = reinterpret_cast<const float4*>(g_r)[(size_t)w * 32 + l];
    reinterpret_cast<float4*>(out)[(size_t)w * 32 + l] =
        make_float4(a0.x * inv + r.x, a0.y * inv + r.y,
                    a1.x * inv + r.z, a1.y * inv + r.w);
    __syncwarp();
    if (l == 0) g_fill[w] = 0;
}

// ---------------------------------------------------------------------------
// HMMA GEMM, fp16 single pass. R16: R14 shape (128x128 CTA, 64x32 warp —
// best smem-bytes/MMA ratio) + 3-stage cp.async pipeline (loads run a full
// chunk ahead; 4 syncs/CTA). K=256 in 4 chunks of 64, SPADK=72.
// LAYER 1: epi relu(+b1l) -> fp16 g_a2
// LAYER 2: epi cols<128 -> fp16 g_t16; cols>=128 -> fp32 g_r (+b2l)
// ---------------------------------------------------------------------------
#define SPADK 72
#define TILE_B (128 * SPADK * 2)      // 18432 bytes (one matrix, one stage)
#define STAGE_B (2 * TILE_B)          // A+B per stage
#define NSTAGE 3
#define GEMM_SMEM (NSTAGE * STAGE_B)  // 110592

template <int LAYER>
__global__ void __launch_bounds__(256)
mma_gemm_kernel(const float* __restrict__ bias, int N) {
    extern __shared__ char dsmem[];
    const uint32_t sbase = smem_to_u32(dsmem);

    const int tid  = threadIdx.x;
    const int lane = tid & 31;
    const int wid  = tid >> 5;
    const int wm   = (wid & 1) * 64;
    const int wn   = (wid >> 1) * 32;
    const int n0   = blockIdx.y * 128;
    const int o0   = blockIdx.x * 128;

    const __half* __restrict__ A = (LAYER == 1) ? g_a1 : g_a2;
    const __half* __restrict__ W = (LAYER == 1) ? g_w1 : g_w2;

    #define A_AT(st) (sbase + (uint32_t)((st) * STAGE_B))
    #define B_AT(st) (sbase + (uint32_t)((st) * STAGE_B + TILE_B))

    // loader: 8 segments of 16B per 64-half row; 32 rows per pass, 4 passes
    const int seg  = tid & 7;
    const int row0 = tid >> 3;        // 0..31

    const int arow = wm + (lane & 15);
    const int acol = (lane >> 4) * 8;
    const int brow = wn + (lane & 7) + ((lane >> 4) << 3);
    const int bcol = ((lane >> 3) & 1) * 8;

    float acc[4][4][4];
#pragma unroll
    for (int mi = 0; mi < 4; mi++)
#pragma unroll
        for (int ni = 0; ni < 4; ni++)
#pragma unroll
            for (int q = 0; q < 4; q++) acc[mi][ni][q] = 0.f;

    auto load_chunk = [&](int kc, int st) {
#pragma unroll
        for (int i = 0; i < 4; i++) {
            int row = row0 + i * 32;
            int n = n0 + row;
            bool ok = n < N;
            size_t ga = (size_t)(ok ? n : 0) * 256 + kc + seg * 8;
            size_t gw = (size_t)(o0 + row) * 256 + kc + seg * 8;
            uint32_t so = (uint32_t)((row * SPADK + seg * 8) * 2);
            cp16(A_AT(st) + so, A + ga, ok);
            cp16(B_AT(st) + so, W + gw, true);
        }
        asm volatile("cp.async.commit_group;");
    };

    // prologue: stages 0,1 in flight
    load_chunk(0, 0);
    load_chunk(64, 1);

    for (int c = 0; c < 4; c++) {
        const int cur = c % NSTAGE;
        if (c < 3) {
            asm volatile("cp.async.wait_group 1;");
        } else {
            asm volatile("cp.async.wait_group 0;");
        }
        __syncthreads();

        // issue next load into the stage freed at iteration c-1
        if (c + 2 < 4) load_chunk((c + 2) * 64, (c + 2) % NSTAGE);

        const uint32_t uA = A_AT(cur);
        const uint32_t uB = B_AT(cur);
#pragma unroll
        for (int ks = 0; ks < 4; ks++) {
            const int k0 = ks * 16;
            uint32_t a[4][4], b[4][2];
#pragma unroll
            for (int mi = 0; mi < 4; mi++)
                ldsm_x4(a[mi], uA + ((arow + mi * 16) * SPADK + k0 + acol) * 2);
#pragma unroll
            for (int nip = 0; nip < 2; nip++) {
                uint32_t bb[4];
                ldsm_x4(bb, uB + ((brow + nip * 16) * SPADK + k0 + bcol) * 2);
                b[nip * 2][0]     = bb[0]; b[nip * 2][1]     = bb[1];
                b[nip * 2 + 1][0] = bb[2]; b[nip * 2 + 1][1] = bb[3];
            }
#pragma unroll
            for (int mi = 0; mi < 4; mi++)
#pragma unroll
                for (int ni = 0; ni < 4; ni++)
                    mma16816(acc[mi][ni], a[mi], b[ni]);
        }
        __syncthreads();
    }

    const int erow = lane >> 2;
    const int ecol = (lane & 3) * 2;
#pragma unroll
    for (int mi = 0; mi < 4; mi++) {
#pragma unroll
        for (int half = 0; half < 2; half++) {
            int n = n0 + wm + mi * 16 + erow + half * 8;
            if (n >= N) continue;
#pragma unroll
            for (int ni = 0; ni < 4; ni++) {
                int col = o0 + wn + ni * 8 + ecol;
                float v0 = acc[mi][ni][half * 2 + 0];
                float v1 = acc[mi][ni][half * 2 + 1];
                if (LAYER == 1) {
                    v0 = fmaxf(v0 + bias[col],     0.f);
                    v1 = fmaxf(v1 + bias[col + 1], 0.f);
                    *reinterpret_cast<__half2*>(g_a2 + (size_t)n * 256 + col) =
                        __halves2half2(__float2half_rn(v0), __float2half_rn(v1));
                } else {
                    if (col < 128) {
                        *reinterpret_cast<__half2*>(g_t16 + (size_t)n * 128 + col) =
                            __halves2half2(__float2half_rn(v0), __float2half_rn(v1));
                    } else {
                        v0 += bias[col - 128];
                        v1 += bias[col - 127];
                        *reinterpret_cast<float2*>(g_r + (size_t)n * 128 + (col - 128)) =
                            make_float2(v0, v1);
                    }
                }
            }
        }
    }
    #undef A_AT
    #undef B_AT
}

// ---------------------------------------------------------------------------
// Launcher — 5 kernel launches; graph-capturable; no static state.
// ---------------------------------------------------------------------------
extern "C" void kernel_launch(void* const* d_in, const int* in_sizes, int n_in,
                              void* d_out, int out_size) {
    const float* x   = (const float*)d_in[0];
    const void*  ei  = d_in[1];
    const float* W1l = (const float*)d_in[2];
    const float* b1l = (const float*)d_in[3];
    const float* W1r = (const float*)d_in[4];
    const float* W2l = (const float*)d_in[5];
    const float* b2l = (const float*)d_in[6];
    const float* W2r = (const float*)d_in[7];
    float* out       = (float*)d_out;

    const int N  = in_sizes[0] / IN_CH;
    const int E  = in_sizes[1] / 2;
    const int EB = (E + 255) / 256;
    const int XB = (N * 64 + 255) / 256;

    cudaFuncSetAttribute(mma_gemm_kernel<1>,
                         cudaFuncAttributeMaxDynamicSharedMemorySize, GEMM_SMEM);
    cudaFuncSetAttribute(mma_gemm_kernel<2>,
                         cudaFuncAttributeMaxDynamicSharedMemorySize, GEMM_SMEM);

    fill_prep_kernel<<<EB + 512 + XB, 256>>>(ei, E, N, EB, W1l, W1r, W2l, W2r, x);
    agg1_kernel<<<(N * 32 + 255) / 256, 256>>>(x, N);
    {
        dim3 grid(2, (N + 127) / 128);
        mma_gemm_kernel<1><<<grid, 256, GEMM_SMEM>>>(b1l, N);
        mma_gemm_kernel<2><<<grid, 256, GEMM_SMEM>>>(b2l, N);
    }
    agg2_kernel<<<(N * 32 + 255) / 256, 256>>>(out, N);
}

// round 17
// speedup vs baseline: 1.0002x; 1.0002x over previous
#include <cuda_runtime.h>
#include <cuda_bf16.h>
#include <cuda_fp16.h>
#include <cstdint>

#define MAX_N 50000
#define MAX_E 800000
#define IN_CH 128
#define HID_CH 256
#define OUT_CH 128
#define DMAX 128

// ---------------------------------------------------------------------------
// Device scratch (allocation-free rule). Zero-initialized at module load;
// g_fill is restored to zero by agg2 every call (deterministic invariant).
// ---------------------------------------------------------------------------
__device__ __align__(16) __half g_a1[(size_t)MAX_N * 256];    // layer-1 A, fp16
__device__ __align__(16) __half g_a2[(size_t)MAX_N * 256];    // layer-2 A, fp16
__device__ __align__(16) __half g_w1[256 * 256];              // composite W fp16
__device__ __align__(16) __half g_w2[256 * 256];
__device__ __align__(16) __half g_x16[(size_t)MAX_N * 128];   // x, fp16 (gather copy)
__device__ __align__(16) __half g_t16[(size_t)MAX_N * 128];   // layer-2 t half, fp16
__device__ float g_r[(size_t)MAX_N * 128];                    // layer-2 r half, fp32
__device__ int g_fill[MAX_N];                                 // degree counters
__device__ int g_colpad[(size_t)MAX_N * DMAX];                // padded CSR

// ---------------------------------------------------------------------------
// Helpers
// ---------------------------------------------------------------------------
__device__ __forceinline__ uint32_t smem_to_u32(const void* p) {
    uint32_t a;
    asm("{ .reg .u64 t; cvta.to.shared.u64 t, %1; cvt.u32.u64 %0, t; }"
        : "=r"(a) : "l"(p));
    return a;
}

__device__ __forceinline__ void ldsm_x4(uint32_t* r, uint32_t addr) {
    asm volatile("ldmatrix.sync.aligned.m8n8.x4.shared.b16 {%0,%1,%2,%3}, [%4];"
        : "=r"(r[0]), "=r"(r[1]), "=r"(r[2]), "=r"(r[3]) : "r"(addr));
}

__device__ __forceinline__ void mma16816(float* d, const uint32_t* a,
                                          const uint32_t* b) {
    asm volatile(
        "mma.sync.aligned.m16n8k16.row.col.f32.f16.f16.f32 "
        "{%0,%1,%2,%3}, {%4,%5,%6,%7}, {%8,%9}, {%0,%1,%2,%3};"
        : "+f"(d[0]), "+f"(d[1]), "+f"(d[2]), "+f"(d[3])
        : "r"(a[0]), "r"(a[1]), "r"(a[2]), "r"(a[3]), "r"(b[0]), "r"(b[1]));
}

__device__ __forceinline__ void cp16(uint32_t dst, const void* src, bool pred) {
    int sz = pred ? 16 : 0;
    asm volatile("cp.async.cg.shared.global [%0], [%1], 16, %2;"
        :: "r"(dst), "l"(src), "r"(sz));
}

// ---------------------------------------------------------------------------
// Kernel 1 (single edge pass): padded-CSR fill with per-block dtype self-sniff
//   blocks [0,EB):          edge fill (slot = atomicAdd(fill[dst]))
//   blocks [EB,EB+512):     fp16 weight prep
//   blocks [EB+512,+XB):    x -> fp16 gather copy
// ---------------------------------------------------------------------------
__global__ void fill_prep_kernel(const void* __restrict__ ei, int E, int N, int EB,
                                 const float* __restrict__ W1l,
                                 const float* __restrict__ W1r,
                                 const float* __restrict__ W2l,
                                 const float* __restrict__ W2r,
                                 const float* __restrict__ x) {
    int b = blockIdx.x, t = threadIdx.x;
    if (b < EB) {
        __shared__ int red[256];
        red[t] = reinterpret_cast<const int*>(ei)[2 * t + 1];
        __syncthreads();
        for (int s = 128; s > 0; s >>= 1) {
            if (t < s) red[t] |= red[t + s];
            __syncthreads();
        }
        bool is64 = (red[0] == 0);
        int e = b * 256 + t;
        if (e >= E) return;
        int src, dst;
        if (is64) {
            src = (int)reinterpret_cast<const long long*>(ei)[e];
            dst = (int)reinterpret_cast<const long long*>(ei)[(size_t)E + e];
        } else {
            src = reinterpret_cast<const int*>(ei)[e];
            dst = reinterpret_cast<const int*>(ei)[(size_t)E + e];
        }
        if ((unsigned)src >= (unsigned)N || (unsigned)dst >= (unsigned)N) return;
        int slot = atomicAdd(&g_fill[dst], 1);
        if (slot < DMAX)
            g_colpad[(size_t)dst * DMAX + slot] = src;
    } else if (b < EB + 512) {
        int wb = b - EB;
        int idx = (wb & 255) * 256 + t;
        int o = idx >> 8, k = idx & 255;
        if (wb < 256) {
            float v = (k < 128) ? W1r[o * 128 + k] : W1l[o * 128 + (k - 128)];
            g_w1[idx] = __float2half_rn(v);
        } else {
            float v = (o < 128) ? W2l[o * 256 + k] : W2r[(o - 128) * 256 + k];
            g_w2[idx] = __float2half_rn(v);
        }
    } else {
        int idx = (b - EB - 512) * 256 + t;
        if (idx >= N * 64) return;
        float2 v = reinterpret_cast<const float2*>(x)[idx];
        reinterpret_cast<__half2*>(g_x16)[idx] = __float22half2_rn(v);
    }
}

// ---------------------------------------------------------------------------
// Layer-1 aggregation (padded CSR, unroll-8) -> single fp16 A:
//   cols 0..127 <- fp16(x[n]);  cols 128..255 <- fp16(mean_{s} x16[s])
// ---------------------------------------------------------------------------
__global__ void agg1_kernel(const float* __restrict__ x, int N) {
    int w = (blockIdx.x * blockDim.x + threadIdx.x) >> 5;
    int l = threadIdx.x & 31;
    if (w >= N) return;
    int deg = g_fill[w];
    int end = min(deg, DMAX);
    const int* col = g_colpad + (size_t)w * DMAX;
    const uint2* X2 = reinterpret_cast<const uint2*>(g_x16);
    float2 a0 = make_float2(0.f, 0.f), a1 = make_float2(0.f, 0.f);
    int i = 0;
    for (; i + 7 < end; i += 8) {
        int s[8];
#pragma unroll
        for (int u = 0; u < 8; u++) s[u] = col[i + u];
        uint2 v[8];
#pragma unroll
        for (int u = 0; u < 8; u++) v[u] = X2[(size_t)s[u] * 32 + l];
#pragma unroll
        for (int u = 0; u < 8; u++) {
            float2 f0 = __half22float2(*reinterpret_cast<__half2*>(&v[u].x));
            float2 f1 = __half22float2(*reinterpret_cast<__half2*>(&v[u].y));
            a0.x += f0.x; a0.y += f0.y; a1.x += f1.x; a1.y += f1.y;
        }
    }
    for (; i < end; i++) {
        uint2 v = X2[(size_t)col[i] * 32 + l];
        float2 f0 = __half22float2(*reinterpret_cast<__half2*>(&v.x));
        float2 f1 = __half22float2(*reinterpret_cast<__half2*>(&v.y));
        a0.x += f0.x; a0.y += f0.y; a1.x += f1.x; a1.y += f1.y;
    }
    float inv = 1.f / fmaxf((float)deg, 1.f);
    size_t base = (size_t)w * 256 + 128 + l * 4;
    *reinterpret_cast<__half2*>(g_a1 + base) =
        __halves2half2(__float2half_rn(a0.x * inv), __float2half_rn(a0.y * inv));
    *reinterpret_cast<__half2*>(g_a1 + base + 2) =
        __halves2half2(__float2half_rn(a1.x * inv), __float2half_rn(a1.y * inv));
    float4 xr = reinterpret_cast<const float4*>(x)[(size_t)w * 32 + l];
    base = (size_t)w * 256 + l * 4;
    *reinterpret_cast<__half2*>(g_a1 + base) =
        __halves2half2(__float2half_rn(xr.x), __float2half_rn(xr.y));
    *reinterpret_cast<__half2*>(g_a1 + base + 2) =
        __halves2half2(__float2half_rn(xr.z), __float2half_rn(xr.w));
}

// ---------------------------------------------------------------------------
// Layer-2 aggregation (padded CSR, unroll-8) + combine; restores g_fill to 0.
//   out[n][c] = mean_{s in N(n)} t16[s][c] + r[n][c]
// ---------------------------------------------------------------------------
__global__ void agg2_kernel(float* __restrict__ out, int N) {
    int w = (blockIdx.x * blockDim.x + threadIdx.x) >> 5;
    int l = threadIdx.x & 31;
    if (w >= N) return;
    int deg = g_fill[w];
    int end = min(deg, DMAX);
    const int* col = g_colpad + (size_t)w * DMAX;
    const uint2* T2 = reinterpret_cast<const uint2*>(g_t16);
    float2 a0 = make_float2(0.f, 0.f), a1 = make_float2(0.f, 0.f);
    int i = 0;
    for (; i + 7 < end; i += 8) {
        int s[8];
#pragma unroll
        for (int u = 0; u < 8; u++) s[u] = col[i + u];
        uint2 v[8];
#pragma unroll
        for (int u = 0; u < 8; u++) v[u] = T2[(size_t)s[u] * 32 + l];
#pragma unroll
        for (int u = 0; u < 8; u++) {
            float2 f0 = __half22float2(*reinterpret_cast<__half2*>(&v[u].x));
            float2 f1 = __half22float2(*reinterpret_cast<__half2*>(&v[u].y));
            a0.x += f0.x; a0.y += f0.y; a1.x += f1.x; a1.y += f1.y;
        }
    }
    for (; i < end; i++) {
        uint2 v = T2[(size_t)col[i] * 32 + l];
        float2 f0 = __half22float2(*reinterpret_cast<__half2*>(&v.x));
        float2 f1 = __half22float2(*reinterpret_cast<__half2*>(&v.y));
        a0.x += f0.x; a0.y += f0.y; a1.x += f1.x; a1.y += f1.y;
    }
    float inv = 1.f / fmaxf((float)deg, 1.f);
    float4 r = reinterpret_cast<const float4*>(g_r)[(size_t)w * 32 + l];
    reinterpret_cast<float4*>(out)[(size_t)w * 32 + l] =
        make_float4(a0.x * inv + r.x, a0.y * inv + r.y,
                    a1.x * inv + r.z, a1.y * inv + r.w);
    __syncwarp();
    if (l == 0) g_fill[w] = 0;
}

// ---------------------------------------------------------------------------
// HMMA GEMM, fp16 single pass. R17: 128x128 CTA / 64x32 warp (best ratio),
// 3-stage cp.async pipeline, ONE __syncthreads per chunk (trailing sync
// removed — stage (c+2)%3 was last read before iteration c's top sync).
// K=256 in 4 chunks of 64, SPADK=72.
// LAYER 1: epi relu(+b1l) -> fp16 g_a2
// LAYER 2: epi cols<128 -> fp16 g_t16; cols>=128 -> fp32 g_r (+b2l)
// ---------------------------------------------------------------------------
#define SPADK 72
#define TILE_B (128 * SPADK * 2)      // 18432 bytes (one matrix, one stage)
#define STAGE_B (2 * TILE_B)          // A+B per stage
#define NSTAGE 3
#define GEMM_SMEM (NSTAGE * STAGE_B)  // 110592

template <int LAYER>
__global__ void __launch_bounds__(256)
mma_gemm_kernel(const float* __restrict__ bias, int N) {
    extern __shared__ char dsmem[];
    const uint32_t sbase = smem_to_u32(dsmem);

    const int tid  = threadIdx.x;
    const int lane = tid & 31;
    const int wid  = tid >> 5;
    const int wm   = (wid & 1) * 64;
    const int wn   = (wid >> 1) * 32;
    const int n0   = blockIdx.y * 128;
    const int o0   = blockIdx.x * 128;

    const __half* __restrict__ A = (LAYER == 1) ? g_a1 : g_a2;
    const __half* __restrict__ W = (LAYER == 1) ? g_w1 : g_w2;

    #define A_AT(st) (sbase + (uint32_t)((st) * STAGE_B))
    #define B_AT(st) (sbase + (uint32_t)((st) * STAGE_B + TILE_B))

    const int seg  = tid & 7;
    const int row0 = tid >> 3;        // 0..31

    const int arow = wm + (lane & 15);
    const int acol = (lane >> 4) * 8;
    const int brow = wn + (lane & 7) + ((lane >> 4) << 3);
    const int bcol = ((lane >> 3) & 1) * 8;

    float acc[4][4][4];
#pragma unroll
    for (int mi = 0; mi < 4; mi++)
#pragma unroll
        for (int ni = 0; ni < 4; ni++)
#pragma unroll
            for (int q = 0; q < 4; q++) acc[mi][ni][q] = 0.f;

    auto load_chunk = [&](int kc, int st) {
#pragma unroll
        for (int i = 0; i < 4; i++) {
            int row = row0 + i * 32;
            int n = n0 + row;
            bool ok = n < N;
            size_t ga = (size_t)(ok ? n : 0) * 256 + kc + seg * 8;
            size_t gw = (size_t)(o0 + row) * 256 + kc + seg * 8;
            uint32_t so = (uint32_t)((row * SPADK + seg * 8) * 2);
            cp16(A_AT(st) + so, A + ga, ok);
            cp16(B_AT(st) + so, W + gw, true);
        }
        asm volatile("cp.async.commit_group;");
    };

    // prologue: stages 0,1 in flight
    load_chunk(0, 0);
    load_chunk(64, 1);

    for (int c = 0; c < 4; c++) {
        const int cur = c % NSTAGE;
        if (c < 3) {
            asm volatile("cp.async.wait_group 1;");
        } else {
            asm volatile("cp.async.wait_group 0;");
        }
        __syncthreads();   // the ONLY barrier per chunk

        // stage (c+2)%3 was last read in iteration c-1, which all warps
        // completed before the sync above -> safe to overwrite now.
        if (c + 2 < 4) load_chunk((c + 2) * 64, (c + 2) % NSTAGE);

        const uint32_t uA = A_AT(cur);
        const uint32_t uB = B_AT(cur);
#pragma unroll
        for (int ks = 0; ks < 4; ks++) {
            const int k0 = ks * 16;
            uint32_t a[4][4], b[4][2];
#pragma unroll
            for (int mi = 0; mi < 4; mi++)
                ldsm_x4(a[mi], uA + ((arow + mi * 16) * SPADK + k0 + acol) * 2);
#pragma unroll
            for (int nip = 0; nip < 2; nip++) {
                uint32_t bb[4];
                ldsm_x4(bb, uB + ((brow + nip * 16) * SPADK + k0 + bcol) * 2);
                b[nip * 2][0]     = bb[0]; b[nip * 2][1]     = bb[1];
                b[nip * 2 + 1][0] = bb[2]; b[nip * 2 + 1][1] = bb[3];
            }
#pragma unroll
            for (int mi = 0; mi < 4; mi++)
#pragma unroll
                for (int ni = 0; ni < 4; ni++)
                    mma16816(acc[mi][ni], a[mi], b[ni]);
        }
        // no trailing __syncthreads (3-stage reuse distance covers it)
    }

    const int erow = lane >> 2;
    const int ecol = (lane & 3) * 2;
#pragma unroll
    for (int mi = 0; mi < 4; mi++) {
#pragma unroll
        for (int half = 0; half < 2; half++) {
            int n = n0 + wm + mi * 16 + erow + half * 8;
            if (n >= N) continue;
#pragma unroll
            for (int ni = 0; ni < 4; ni++) {
                int col = o0 + wn + ni * 8 + ecol;
                float v0 = acc[mi][ni][half * 2 + 0];
                float v1 = acc[mi][ni][half * 2 + 1];
                if (LAYER == 1) {
                    v0 = fmaxf(v0 + bias[col],     0.f);
                    v1 = fmaxf(v1 + bias[col + 1], 0.f);
                    *reinterpret_cast<__half2*>(g_a2 + (size_t)n * 256 + col) =
                        __halves2half2(__float2half_rn(v0), __float2half_rn(v1));
                } else {
                    if (col < 128) {
                        *reinterpret_cast<__half2*>(g_t16 + (size_t)n * 128 + col) =
                            __halves2half2(__float2half_rn(v0), __float2half_rn(v1));
                    } else {
                        v0 += bias[col - 128];
                        v1 += bias[col - 127];
                        *reinterpret_cast<float2*>(g_r + (size_t)n * 128 + (col - 128)) =
                            make_float2(v0, v1);
                    }
                }
            }
        }
    }
    #undef A_AT
    #undef B_AT
}

// ---------------------------------------------------------------------------
// Launcher — 5 kernel launches; graph-capturable; no static state.
// ---------------------------------------------------------------------------
extern "C" void kernel_launch(void* const* d_in, const int* in_sizes, int n_in,
                              void* d_out, int out_size) {
    const float* x   = (const float*)d_in[0];
    const void*  ei  = d_in[1];
    const float* W1l = (const float*)d_in[2];
    const float* b1l = (const float*)d_in[3];
    const float* W1r = (const float*)d_in[4];
    const float* W2l = (const float*)d_in[5];
    const float* b2l = (const float*)d_in[6];
    const float* W2r = (const float*)d_in[7];
    float* out       = (float*)d_out;

    const int N  = in_sizes[0] / IN_CH;
    const int E  = in_sizes[1] / 2;
    const int EB = (E + 255) / 256;
    const int XB = (N * 64 + 255) / 256;

    cudaFuncSetAttribute(mma_gemm_kernel<1>,
                         cudaFuncAttributeMaxDynamicSharedMemorySize, GEMM_SMEM);
    cudaFuncSetAttribute(mma_gemm_kernel<2>,
                         cudaFuncAttributeMaxDynamicSharedMemorySize, GEMM_SMEM);

    fill_prep_kernel<<<EB + 512 + XB, 256>>>(ei, E, N, EB, W1l, W1r, W2l, W2r, x);
    agg1_kernel<<<(N * 32 + 255) / 256, 256>>>(x, N);
    {
        dim3 grid(2, (N + 127) / 128);
        mma_gemm_kernel<1><<<grid, 256, GEMM_SMEM>>>(b1l, N);
        mma_gemm_kernel<2><<<grid, 256, GEMM_SMEM>>>(b2l, N);
    }
    agg2_kernel<<<(N * 32 + 255) / 256, 256>>>(out, N);
}